// round 5
// baseline (speedup 1.0000x reference)
#include <cuda_runtime.h>

// DCT_26688926778120  — warp-cooperative version
// x: (B=8, C=3, T=32, H=256, W=256) fp32 -> out: (B,T,1024,8,8) fp32
// 8 lanes per 8x8 block: lane ln owns image row ln of the block.
// Row DCT in-lane, 8x8 xor-shuffle transpose, column DCT in-lane.
// ~50 regs/thread -> 4 CTAs/SM (50% occ) for latency hiding; pure HBM stream.

#define C1 1.9615705608064609f
#define C2 1.8477590650225735f
#define C3 1.6629392246050905f
#define C4 1.4142135623730951f
#define C5 1.1111404660392044f
#define C6 0.7653668647301796f
#define C7 0.3901806440322565f

__device__ __forceinline__ void dct8(const float v[8], float o[8])
{
    float s0 = v[0] + v[7], s1 = v[1] + v[6], s2 = v[2] + v[5], s3 = v[3] + v[4];
    float d0 = v[0] - v[7], d1 = v[1] - v[6], d2 = v[2] - v[5], d3 = v[3] - v[4];
    o[0] = 2.0f * ((s0 + s3) + (s1 + s2));
    o[4] = C4   * ((s0 + s3) - (s1 + s2));
    o[2] = C2 * (s0 - s3) + C6 * (s1 - s2);
    o[6] = C6 * (s0 - s3) - C2 * (s1 - s2);
    o[1] = C1 * d0 + C3 * d1 + C5 * d2 + C7 * d3;
    o[3] = C3 * d0 - C7 * d1 - C1 * d2 - C5 * d3;
    o[5] = C5 * d0 - C1 * d1 + C7 * d2 + C3 * d3;
    o[7] = C7 * d0 - C5 * d1 + C3 * d2 - C1 * d3;
}

__global__ __launch_bounds__(256, 4)
void dct_kernel(const float* __restrict__ x, float* __restrict__ out)
{
    const float WR = 0.2989f, WG = 0.587f, WB = 0.114f;

    unsigned gtid  = blockIdx.x * 256u + threadIdx.x;  // [0, 2097152)
    unsigned ln    = gtid & 7u;                        // row within block
    unsigned group = gtid >> 3;                        // 8x8 block id [0, 262144)

    unsigned wbi = group & 31u;
    unsigned hbi = (group >> 5) & 31u;
    unsigned tt  = (group >> 10) & 31u;
    unsigned bb  = group >> 15;

    const size_t plane   = 65536u;            // 256*256
    const size_t cstride = 32u * plane;       // channel stride (2,097,152)

    const float* p = x + ((size_t)(bb * 96u + tt)) * plane
                       + (size_t)(hbi * 8u + ln) * 256u + (size_t)wbi * 8u;

    // 6 independent 16B loads (front-batched for MLP)
    float4 r0 = *(const float4*)(p);
    float4 r1 = *(const float4*)(p + 4);
    float4 g0 = *(const float4*)(p + cstride);
    float4 g1 = *(const float4*)(p + cstride + 4);
    float4 b0 = *(const float4*)(p + 2u * cstride);
    float4 b1 = *(const float4*)(p + 2u * cstride + 4);

    float g[8];
    g[0] = WR * r0.x + WG * g0.x + WB * b0.x;
    g[1] = WR * r0.y + WG * g0.y + WB * b0.y;
    g[2] = WR * r0.z + WG * g0.z + WB * b0.z;
    g[3] = WR * r0.w + WG * g0.w + WB * b0.w;
    g[4] = WR * r1.x + WG * g1.x + WB * b1.x;
    g[5] = WR * r1.y + WG * g1.y + WB * b1.y;
    g[6] = WR * r1.z + WG * g1.z + WB * b1.z;
    g[7] = WR * r1.w + WG * g1.w + WB * b1.w;

    // Row DCT (lane ln = matrix row ln): y[c] = (D * row)[c]
    float y[8];
    dct8(g, y);

    // 8x8 transpose across the 8-lane group via xor shuffles.
    // After this, y[n] on lane ln == original y[n] of lane n at slot ln,
    // i.e. lane ln holds column ln of the row-DCT'd block.
#pragma unroll
    for (int m = 1; m < 8; m <<= 1) {
        float t[8];
#pragma unroll
        for (int i = 0; i < 8; ++i) t[i] = y[i ^ m];
#pragma unroll
        for (int i = 0; i < 8; ++i) {
            float o = __shfl_xor_sync(0xFFFFFFFFu, t[i], m, 32);
            y[i] = (((i ^ (int)ln) & m) != 0) ? o : y[i];
        }
    }

    // Column DCT: lane ln now holds z[n] = Y[n][ln]; out[k][ln] = (D*z)[k]
    float a[8];
    dct8(y, a);

    // out block base = group*64; lane writes column ln: out[k*8 + ln]
    float* op = out + (size_t)group * 64u + ln;
#pragma unroll
    for (int k = 0; k < 8; ++k)
        op[8 * k] = a[k];
}

extern "C" void kernel_launch(void* const* d_in, const int* in_sizes, int n_in,
                              void* d_out, int out_size)
{
    const float* x = (const float*)d_in[0];
    float* out = (float*)d_out;
    // 262,144 blocks * 8 threads = 2,097,152 threads
    dct_kernel<<<8192, 256>>>(x, out);
}